// round 14
// baseline (speedup 1.0000x reference)
#include <cuda_runtime.h>
#include <cuda_bf16.h>
#include <math.h>

#define BQ   128
#define SQ   32
#define INQ  512
#define HQ   1024
#define OUTQ 512
#define NQ   16384
#define WQ   128
#define CQ   899
#define CP   960
#define K1   1664
#define KR   1152
#define G4   4096
#define HRP  576
#define HOW  1088
#define HOWP 1152
#define NCHUNK 128
#define NZ   4

// ---------------- device globals ----------------
__device__ float sc_mem[NQ * WQ];
__device__ __nv_bfloat16 sc_WfH[(long long)G4 * K1];
__device__ __nv_bfloat16 sc_WfL[(long long)G4 * K1];
__device__ __nv_bfloat16 sc_xH[(long long)SQ * BQ * INQ];
__device__ __nv_bfloat16 sc_xL[(long long)SQ * BQ * INQ];
__device__ float sc_bg[G4];
__device__ float sc_WoutP[CP * HQ];
__device__ float sc_HW[HRP * CP];
__device__ __nv_bfloat16 sc_HOWH[(long long)HOWP * HQ];
__device__ __nv_bfloat16 sc_HOWL[(long long)HOWP * HQ];
__device__ float sc_HOb[HOW];
__device__ float sc_g4[NZ * BQ * G4];
__device__ float sc_ho8[8 * BQ * HOWP];
__device__ float sc_h[BQ * HQ];
__device__ float sc_c[BQ * HQ];
__device__ __nv_bfloat16 sc_AH[BQ * KR];
__device__ __nv_bfloat16 sc_AL[BQ * KR];
__device__ float sc_rw[BQ * NQ];
__device__ __nv_bfloat16 sc_rwH[(long long)BQ * NQ];
__device__ __nv_bfloat16 sc_rwL[(long long)BQ * NQ];
__device__ __nv_bfloat16 sc_wwH[(long long)BQ * NQ];
__device__ __nv_bfloat16 sc_wwL[(long long)BQ * NQ];
__device__ __nv_bfloat16 sc_keysH[2 * BQ * WQ];
__device__ __nv_bfloat16 sc_keysL[2 * BQ * WQ];
__device__ __nv_bfloat16 sc_memnH[NQ * WQ];
__device__ __nv_bfloat16 sc_memnL[NQ * WQ];
__device__ __nv_bfloat16 sc_erH[BQ * WQ];
__device__ __nv_bfloat16 sc_erL[BQ * WQ];
__device__ __nv_bfloat16 sc_adH[BQ * WQ];
__device__ __nv_bfloat16 sc_adL[BQ * WQ];
__device__ float sc_beta[2 * BQ];
__device__ float sc_gamma[2 * BQ];
__device__ float sc_sim[2 * BQ * NQ];
__device__ float sc_rvpart[NCHUNK * BQ * WQ];

// ---------------- helpers ----------------
__device__ __forceinline__ float sigmoidf_(float x) { return 1.0f / (1.0f + expf(-x)); }
__device__ __forceinline__ float softplusf_(float x) { return x > 20.0f ? x : log1pf(expf(x)); }

__device__ __forceinline__ void bsplit(float v, __nv_bfloat16* h, __nv_bfloat16* l) {
    __nv_bfloat16 hi = __float2bfloat16(v);
    *h = hi;
    *l = __float2bfloat16(v - __bfloat162float(hi));
}

__device__ __forceinline__ void st_bf2(__nv_bfloat16* p, __nv_bfloat16 a, __nv_bfloat16 b) {
    __nv_bfloat162 t;
    t.x = a;
    t.y = b;
    *(__nv_bfloat162*)p = t;
}

__device__ __forceinline__ unsigned sptr(const void* p) {
    return (unsigned)__cvta_generic_to_shared(p);
}

__device__ __forceinline__ void ldm_x4(unsigned* r, unsigned a) {
    asm volatile("ldmatrix.sync.aligned.m8n8.x4.shared.b16 {%0,%1,%2,%3}, [%4];"
        : "=r"(r[0]), "=r"(r[1]), "=r"(r[2]), "=r"(r[3]) : "r"(a));
}

__device__ __forceinline__ void ldm_x2(unsigned* r, unsigned a) {
    asm volatile("ldmatrix.sync.aligned.m8n8.x2.shared.b16 {%0,%1}, [%2];"
        : "=r"(r[0]), "=r"(r[1]) : "r"(a));
}

__device__ __forceinline__ void ldm_x4t(unsigned* r, unsigned a) {
    asm volatile("ldmatrix.sync.aligned.m8n8.x4.trans.shared.b16 {%0,%1,%2,%3}, [%4];"
        : "=r"(r[0]), "=r"(r[1]), "=r"(r[2]), "=r"(r[3]) : "r"(a));
}

__device__ __forceinline__ void ldm_x2t(unsigned* r, unsigned a) {
    asm volatile("ldmatrix.sync.aligned.m8n8.x2.trans.shared.b16 {%0,%1}, [%2];"
        : "=r"(r[0]), "=r"(r[1]) : "r"(a));
}

__device__ __forceinline__ void mma_bf16(float* d, const unsigned* a, const unsigned* b) {
    asm volatile("mma.sync.aligned.m16n8k16.row.col.f32.bf16.bf16.f32 "
        "{%0,%1,%2,%3}, {%4,%5,%6,%7}, {%8,%9}, {%0,%1,%2,%3};"
        : "+f"(d[0]), "+f"(d[1]), "+f"(d[2]), "+f"(d[3])
        : "r"(a[0]), "r"(a[1]), "r"(a[2]), "r"(a[3]), "r"(b[0]), "r"(b[1]));
}

__device__ __forceinline__ void cp16(unsigned dst, const void* src) {
    asm volatile("cp.async.cg.shared.global [%0], [%1], 16;" :: "r"(dst), "l"(src));
}
__device__ __forceinline__ void cp_commit() { asm volatile("cp.async.commit_group;"); }
__device__ __forceinline__ void cp_wait0() { asm volatile("cp.async.wait_group 0;"); }
__device__ __forceinline__ void cp_wait1() { asm volatile("cp.async.wait_group 1;"); }

__device__ __forceinline__ float blockSum128(float v, float* sh) {
    #pragma unroll
    for (int o = 16; o; o >>= 1) v += __shfl_xor_sync(0xffffffffu, v, o);
    if ((threadIdx.x & 31) == 0) sh[threadIdx.x >> 5] = v;
    __syncthreads();
    float r = sh[0] + sh[1] + sh[2] + sh[3];
    __syncthreads();
    return r;
}

__device__ __forceinline__ float hw_elem(int r, int k,
    const float* rkW, const float* rbW, const float* rgW,
    const float* wkW, const float* wbW, const float* wgW,
    const float* erW, const float* adW) {
    if (k >= CQ || r >= 516) return 0.0f;
    if (r < 128) return rkW[r * CQ + k];
    if (r == 128) return rbW[k];
    if (r == 129) return rgW[k];
    if (r < 258) return wkW[(r - 130) * CQ + k];
    if (r == 258) return wbW[k];
    if (r == 259) return wgW[k];
    if (r < 388) return erW[(r - 260) * CQ + k];
    return adW[(r - 388) * CQ + k];
}

__device__ __forceinline__ float hb_elem(int r,
    const float* rkb, const float* rbb, const float* rgb,
    const float* wkb, const float* wbb, const float* wgb,
    const float* erb, const float* adb) {
    if (r < 128) return rkb[r];
    if (r == 128) return rbb[0];
    if (r == 129) return rgb[0];
    if (r < 258) return wkb[r - 130];
    if (r == 258) return wbb[0];
    if (r == 259) return wgb[0];
    if (r < 388) return erb[r - 260];
    if (r < 516) return adb[r - 388];
    return 0.0f;
}

// ---------------- prologue ----------------
__global__ void k_setup_w(const float* __restrict__ Wih, const float* __restrict__ Whh,
                          const float* __restrict__ bih, const float* __restrict__ bhh,
                          const float* __restrict__ Wout,
                          const float* rkW, const float* rbW, const float* rgW,
                          const float* wkW, const float* wbW, const float* wgW,
                          const float* erW, const float* adW) {
    long long i = (long long)blockIdx.x * blockDim.x + threadIdx.x;
    const long long NW = (long long)G4 * K1;
    const long long ND = (long long)CP * HQ;
    const long long NE = (long long)HRP * CP;
    if (i < NW) {
        int r = (int)(i / K1);
        int k = (int)(i % K1);
        int src = (r & 3) * HQ + (r >> 2);
        float v = (k < INQ + WQ) ? Wih[src * (INQ + WQ) + k] : Whh[src * HQ + (k - INQ - WQ)];
        __nv_bfloat16 h, l;
        bsplit(v, &h, &l);
        sc_WfH[i] = h;
        sc_WfL[i] = l;
        return;
    }
    i -= NW;
    if (i < G4) {
        int r = (int)i;
        int src = (r & 3) * HQ + (r >> 2);
        sc_bg[r] = bih[src] + bhh[src];
        return;
    }
    i -= G4;
    if (i < ND) {
        int r = (int)(i / HQ);
        sc_WoutP[i] = (r < CQ) ? Wout[(long long)r * HQ + (i % HQ)] : 0.0f;
        return;
    }
    i -= ND;
    if (i < NE) {
        int r = (int)(i / CP);
        int k = (int)(i % CP);
        sc_HW[i] = hw_elem(r, k, rkW, rbW, rgW, wkW, wbW, wgW, erW, adW);
        return;
    }
}

__global__ void k_setup_x(const float* __restrict__ x) {
    long long i = (long long)blockIdx.x * blockDim.x + threadIdx.x;
    const long long NX = (long long)SQ * BQ * INQ;
    if (i < NX) {
        int k = (int)(i % INQ);
        long long sb = i / INQ;
        int b = (int)(sb % BQ);
        int s = (int)(sb / BQ);
        float v = x[((long long)b * SQ + s) * INQ + k];
        __nv_bfloat16 h, l;
        bsplit(v, &h, &l);
        sc_xH[i] = h;
        sc_xL[i] = l;
        return;
    }
    i -= NX;
    const long long NP = (long long)(HOWP - HOW) * HQ;
    if (i < 2 * NP) {
        __nv_bfloat16 z = __float2bfloat16(0.0f);
        long long j = (i < NP) ? i : (i - NP);
        long long idx = (long long)(HOW + (int)(j / HQ)) * HQ + (int)(j % HQ);
        if (i < NP) sc_HOWH[idx] = z;
        else        sc_HOWL[idx] = z;
    }
}

__global__ __launch_bounds__(256) void k_initmem(const float* __restrict__ memory) {
    if (blockIdx.x < 2048) {
        int row = blockIdx.x * 8 + (threadIdx.x >> 5);
        int lane = threadIdx.x & 31;
        const float* src = memory + (long long)row * WQ;
        float v[4];
        float s = 0.f;
        #pragma unroll
        for (int i = 0; i < 4; i++) { v[i] = src[lane + 32 * i]; s += v[i] * v[i]; }
        #pragma unroll
        for (int o = 16; o; o >>= 1) s += __shfl_xor_sync(0xffffffffu, s, o);
        float inv = 1.0f / fmaxf(sqrtf(s), 1e-12f);
        #pragma unroll
        for (int i = 0; i < 4; i++) {
            long long o = (long long)row * WQ + lane + 32 * i;
            sc_mem[o] = v[i];
            __nv_bfloat16 h, l;
            bsplit(v[i] * inv, &h, &l);
            sc_memnH[o] = h;
            sc_memnL[o] = l;
        }
    } else {
        long long base = (long long)(blockIdx.x - 2048) * 256 + threadIdx.x;
        if (base < (long long)BQ * NQ) { sc_rw[base] = 1.0f / (float)NQ; return; }
        base -= (long long)BQ * NQ;
        if (base < (long long)BQ * NQ / 2) { ((unsigned*)sc_rwH)[base] = 0x38803880u; return; }
        base -= (long long)BQ * NQ / 2;
        if (base < (long long)BQ * NQ / 2) { ((unsigned*)sc_rwL)[base] = 0u; return; }
        base -= (long long)BQ * NQ / 2;
        if (base < BQ * HQ) { sc_h[base] = 0.0f; return; }
        base -= BQ * HQ;
        if (base < BQ * HQ) { sc_c[base] = 0.0f; return; }
        base -= BQ * HQ;
        if (base < BQ * KR / 2) { ((unsigned*)sc_AH)[base] = 0u; return; }
        base -= BQ * KR / 2;
        if (base < BQ * KR / 2) { ((unsigned*)sc_AL)[base] = 0u; return; }
    }
}

__global__ __launch_bounds__(128) void k_biases(const float* bout, const float* pW, const float* pb,
    const float* rkW, const float* rbW, const float* rgW,
    const float* wkW, const float* wbW, const float* wgW,
    const float* erW, const float* adW,
    const float* rkb, const float* rbb, const float* rgb,
    const float* wkb, const float* wbb, const float* wgb,
    const float* erb, const float* adb) {
    __shared__ float sh[4];
    int r = blockIdx.x;
    int t = threadIdx.x;
    float s = 0.f;
    if (r < HRP) {
        for (int c = t; c < CQ; c += 128)
            s += hw_elem(r, c, rkW, rbW, rgW, wkW, wbW, wgW, erW, adW) * bout[c];
        s = blockSum128(s, sh);
        if (t == 0) sc_HOb[r] = s + hb_elem(r, rkb, rbb, rgb, wkb, wbb, wgb, erb, adb);
    } else {
        int o = r - HRP;
        for (int c = t; c < OUTQ; c += 128) s += pW[o * OUTQ + c] * bout[c];
        s = blockSum128(s, sh);
        if (t == 0) sc_HOb[r] = s + pb[o];
    }
}

__global__ __launch_bounds__(256) void k_fold(const float* __restrict__ pW,
                                              const float* __restrict__ Wout) {
    __shared__ float As[32][36];
    __shared__ float Bs[32][36];
    int tid = threadIdx.x;
    int n0 = blockIdx.x * 32;
    int second = (blockIdx.y >= 18) ? 1 : 0;
    int m0 = second ? (blockIdx.y - 18) * 32 : blockIdx.y * 32;
    const float* A = second ? pW : sc_HW;
    const float* B = second ? Wout : sc_WoutP;
    int lda = second ? OUTQ : CP;
    int K = second ? OUTQ : CP;
    int dstRow = second ? HRP : 0;
    int rowL = tid >> 3;
    int k4 = (tid & 7) * 4;
    int tm = tid & 7;
    int tn = tid >> 3;
    float acc[4] = {};
    for (int k0 = 0; k0 < K; k0 += 32) {
        float4 a = *(const float4*)(A + (long long)(m0 + rowL) * lda + k0 + k4);
        float4 b = *(const float4*)(B + (long long)(k0 + rowL) * HQ + n0 + k4);
        As[rowL][k4 + 0] = a.x; As[rowL][k4 + 1] = a.y; As[rowL][k4 + 2] = a.z; As[rowL][k4 + 3] = a.w;
        Bs[rowL][k4 + 0] = b.x; Bs[rowL][k4 + 1] = b.y; Bs[rowL][k4 + 2] = b.z; Bs[rowL][k4 + 3] = b.w;
        __syncthreads();
        #pragma unroll
        for (int k = 0; k < 32; k++) {
            float bv = Bs[k][tn];
            #pragma unroll
            for (int i = 0; i < 4; i++) acc[i] = fmaf(As[tm * 4 + i][k], bv, acc[i]);
        }
        __syncthreads();
    }
    #pragma unroll
    for (int i = 0; i < 4; i++) {
        long long idx = (long long)(dstRow + m0 + tm * 4 + i) * HQ + n0 + tn;
        __nv_bfloat16 h;
        __nv_bfloat16 l;
        bsplit(acc[i], &h, &l);
        sc_HOWH[idx] = h;
        sc_HOWL[idx] = l;
    }
}

// ---------------- shared MMA tile machinery ----------------
#define L_ROWHW 40
#define L_SEGB  (128 * L_ROWHW * 2)
#define L_BUFB  (4 * L_SEGB)

// stage one 32-K chunk; kind 0 = lstm (x|rv|h A operand, Wf B), kind 1 = ho (h-only A, HOW B)
__device__ __forceinline__ void mix_stage(char* dsm, int buf, int c, int n0, int kbase, int s,
                                          int kind, int tid) {
    for (int u = tid; u < 2048; u += 256) {
        int seg = u >> 9;
        int rem = u & 511;
        int row = rem >> 2;
        int unit = rem & 3;
        unsigned dst = sptr(dsm + buf * L_BUFB + seg * L_SEGB + row * (L_ROWHW * 2) + unit * 16);
        int kk = kbase + c * 32 + unit * 8;
        const __nv_bfloat16* base;
        if (kind == 0) {
            if (seg < 2) {
                if (kk < INQ) base = ((seg == 0) ? sc_xH : sc_xL) + ((long long)s * BQ + row) * INQ + kk;
                else          base = ((seg == 0) ? sc_AH : sc_AL) + (long long)row * KR + (kk - INQ);
            } else {
                base = ((seg == 2) ? sc_WfH : sc_WfL) + (long long)(n0 + row) * K1 + kk;
            }
        } else {
            if (seg == 0)      base = sc_AH + (long long)row * KR + WQ + kk;
            else if (seg == 1) base = sc_AL + (long long)row * KR + WQ + kk;
            else if (seg == 2) base = sc_HOWH + (long long)(n0 + row) * HQ + kk;
            else               base = sc_HOWL + (long long)(n0 + row) * HQ + kk;
        }
        cp16(dst, base);
    }
    cp_commit();
}

__device__ __forceinline__ void mix_core(char* dsm, int n0, int kbase, int nch, int s, int kind,
                                         float* dst, int ldc, int tid) {
    int w = tid >> 5;
    int lane = tid & 31;
    int mBase = (w >> 2) * 64;
    int nBase = (w & 3) * 32;
    float acc[4][4][4] = {};
    mix_stage(dsm, 0, 0, n0, kbase, s, kind, tid);
    #pragma unroll 1
    for (int c = 0; c < nch; c++) {
        if (c < nch - 1) {
            mix_stage(dsm, (c + 1) & 1, c + 1, n0, kbase, s, kind, tid);
            cp_wait1();
        } else {
            cp_wait0();
        }
        __syncthreads();
        char* B0 = dsm + (c & 1) * L_BUFB;
        __nv_bfloat16* AHs = (__nv_bfloat16*)B0;
        __nv_bfloat16* ALs = (__nv_bfloat16*)(B0 + L_SEGB);
        __nv_bfloat16* BHs = (__nv_bfloat16*)(B0 + 2 * L_SEGB);
        __nv_bfloat16* BLs = (__nv_bfloat16*)(B0 + 3 * L_SEGB);
        #pragma unroll
        for (int kk = 0; kk < 2; kk++) {
            unsigned ah[4][4];
            unsigned al[4][4];
            int acol = kk * 16 + (lane >> 4) * 8;
            #pragma unroll
            for (int mt = 0; mt < 4; mt++) {
                int ar = mBase + mt * 16 + (lane & 15);
                ldm_x4(ah[mt], sptr(AHs + ar * L_ROWHW + acol));
                ldm_x4(al[mt], sptr(ALs + ar * L_ROWHW + acol));
            }
            int q = lane & 15;
            int bcol = kk * 16 + (q >> 3) * 8;
            #pragma unroll
            for (int nt = 0; nt < 4; nt++) {
                int br = nBase + nt * 8 + (q & 7);
                unsigned bh[2];
                unsigned bl[2];
                ldm_x2(bh, sptr(BHs + br * L_ROWHW + bcol));
                ldm_x2(bl, sptr(BLs + br * L_ROWHW + bcol));
                #pragma unroll
                for (int mt = 0; mt < 4; mt++) {
                    mma_bf16(acc[mt][nt], ah[mt], bh);
                    mma_bf16(acc[mt][nt], ah[mt], bl);
                    mma_bf16(acc[mt][nt], al[mt], bh);
                }
            }
        }
        __syncthreads();
    }
    #pragma unroll
    for (int mt = 0; mt < 4; mt++) {
        int r = mBase + mt * 16 + (lane >> 2);
        #pragma unroll
        for (int nt = 0; nt < 4; nt++) {
            int cc = n0 + nBase + nt * 8 + (lane & 3) * 2;
            *(float2*)&dst[(long long)r * ldc + cc] = make_float2(acc[mt][nt][0], acc[mt][nt][1]);
            *(float2*)&dst[(long long)(r + 8) * ldc + cc] = make_float2(acc[mt][nt][2], acc[mt][nt][3]);
        }
    }
}

// standalone LSTM slices (prologue xh + per-step rv). mode 0: z=0..2 xh; mode 1: rv
__global__ __launch_bounds__(256) void k_lstm_mma(int s, int mode) {
    extern __shared__ char dsm[];
    int n0 = blockIdx.x * 128;
    int z = blockIdx.z;
    int kbase, nch, slot;
    if (mode == 0) {
        if (z == 0)      { kbase = 0;    nch = 16; slot = 0; }
        else if (z == 1) { kbase = 640;  nch = 16; slot = 2; }
        else             { kbase = 1152; nch = 16; slot = 3; }
    } else             { kbase = 512;  nch = 4;  slot = 1; }
    mix_core(dsm, n0, kbase, nch, s, 0, sc_g4 + (long long)slot * BQ * G4, G4, threadIdx.x);
}

// merged ho(s) + lstm-xh(sNext): blocks 0..71 ho, 72..167 lstm
__global__ __launch_bounds__(256) void k_homix(int sNext, int doLstm) {
    extern __shared__ char dsm[];
    int bid = blockIdx.x;
    if (bid < 72) {
        int n0 = (bid % 9) * 128;
        int z = bid / 9;
        mix_core(dsm, n0, z * 128, 4, 0, 1, sc_ho8 + (long long)z * BQ * HOWP, HOWP, threadIdx.x);
    } else {
        if (!doLstm) return;
        int b2 = bid - 72;
        int n0 = (b2 & 31) * 128;
        int zz = b2 >> 5;
        int kbase = (zz == 0) ? 0 : ((zz == 1) ? 640 : 1152);
        int slot = (zz == 0) ? 0 : ((zz == 1) ? 2 : 3);
        mix_core(dsm, n0, kbase, 16, sNext, 0, sc_g4 + (long long)slot * BQ * G4, G4, threadIdx.x);
    }
}

__global__ __launch_bounds__(128) void k_hored(float* __restrict__ out, int s) {
    __shared__ float hrow[HRP];
    __shared__ float sh[4];
    int b = blockIdx.x;
    int t = threadIdx.x;
    for (int n = t; n < HOW; n += 128) {
        float v = sc_HOb[n];
        #pragma unroll
        for (int z = 0; z < 8; z++)
            v += sc_ho8[((long long)z * BQ + b) * HOWP + n];
        if (n < HRP) hrow[n] = v;
        else out[((long long)b * SQ + s) * OUTQ + (n - HRP)] = v;
    }
    __syncthreads();
    float rk = hrow[t];
    float wk = hrow[130 + t];
    float nr2 = blockSum128(rk * rk, sh);
    float nw2 = blockSum128(wk * wk, sh);
    __nv_bfloat16 h;
    __nv_bfloat16 l;
    bsplit(rk / fmaxf(sqrtf(nr2), 1e-12f), &h, &l);
    sc_keysH[b * WQ + t] = h;
    sc_keysL[b * WQ + t] = l;
    bsplit(wk / fmaxf(sqrtf(nw2), 1e-12f), &h, &l);
    sc_keysH[(128 + b) * WQ + t] = h;
    sc_keysL[(128 + b) * WQ + t] = l;
    if (t == 0) {
        sc_beta[b] = softplusf_(hrow[128]);
        sc_gamma[b] = 1.0f + softplusf_(hrow[129]);
        sc_beta[128 + b] = softplusf_(hrow[258]);
        sc_gamma[128 + b] = 1.0f + softplusf_(hrow[259]);
    }
    bsplit(sigmoidf_(hrow[260 + t]), &h, &l);
    sc_erH[b * WQ + t] = h;
    sc_erL[b * WQ + t] = l;
    bsplit(tanhf(hrow[388 + t]), &h, &l);
    sc_adH[b * WQ + t] = h;
    sc_adL[b * WQ + t] = l;
}

// ---------------- sim GEMM ----------------
__global__ __launch_bounds__(256, 1) void k_sim_mma() {
    extern __shared__ char dsm[];
    __nv_bfloat16* AHs = (__nv_bfloat16*)dsm;
    __nv_bfloat16* ALs = (__nv_bfloat16*)(dsm + 34816);
    __nv_bfloat16* BHs = (__nv_bfloat16*)(dsm + 69632);
    __nv_bfloat16* BLs = (__nv_bfloat16*)(dsm + 104448);
    int tid = threadIdx.x;
    int w = tid >> 5;
    int lane = tid & 31;
    int n0 = blockIdx.x * 128;
    int m0 = blockIdx.y * 128;
    for (int u = tid; u < 8192; u += 256) {
        int seg = u >> 11;
        int rem = u & 2047;
        int row = rem >> 4;
        int unit = rem & 15;
        unsigned dst = sptr(dsm + seg * 34816 + row * 272 + unit * 16);
        const char* src;
        if (seg == 0)      src = (const char*)sc_keysH + ((long long)(m0 + row) * WQ + unit * 8) * 2;
        else if (seg == 1) src = (const char*)sc_keysL + ((long long)(m0 + row) * WQ + unit * 8) * 2;
        else if (seg == 2) src = (const char*)sc_memnH + ((long long)(n0 + row) * WQ + unit * 8) * 2;
        else               src = (const char*)sc_memnL + ((long long)(n0 + row) * WQ + unit * 8) * 2;
        cp16(dst, src);
    }
    cp_commit();
    cp_wait0();
    __syncthreads();
    int mBase = (w >> 2) * 64;
    int nBase = (w & 3) * 32;
    float acc[4][4][4] = {};
    #pragma unroll
    for (int kk = 0; kk < 8; kk++) {
        unsigned ah[4][4];
        unsigned al[4][4];
        int acol = kk * 16 + (lane >> 4) * 8;
        #pragma unroll
        for (int mt = 0; mt < 4; mt++) {
            int ar = mBase + mt * 16 + (lane & 15);
            ldm_x4(ah[mt], sptr(AHs + ar * 136 + acol));
            ldm_x4(al[mt], sptr(ALs + ar * 136 + acol));
        }
        int q = lane & 15;
        int bcol = kk * 16 + (q >> 3) * 8;
        #pragma unroll
        for (int nt = 0; nt < 4; nt++) {
            int br = nBase + nt * 8 + (q & 7);
            unsigned bh[2];
            unsigned bl[2];
            ldm_x2(bh, sptr(BHs + br * 136 + bcol));
            ldm_x2(bl, sptr(BLs + br * 136 + bcol));
            #pragma unroll
            for (int mt = 0; mt < 4; mt++) {
                mma_bf16(acc[mt][nt], ah[mt], bh);
                mma_bf16(acc[mt][nt], ah[mt], bl);
                mma_bf16(acc[mt][nt], al[mt], bh);
            }
        }
    }
    #pragma unroll
    for (int mt = 0; mt < 4; mt++) {
        int r = m0 + mBase + mt * 16 + (lane >> 2);
        #pragma unroll
        for (int nt = 0; nt < 4; nt++) {
            int cc = n0 + nBase + nt * 8 + (lane & 3) * 2;
            *(float2*)&sc_sim[(long long)r * NQ + cc] = make_float2(acc[mt][nt][0], acc[mt][nt][1]);
            *(float2*)&sc_sim[(long long)(r + 8) * NQ + cc] = make_float2(acc[mt][nt][2], acc[mt][nt][3]);
        }
    }
}

// ---------------- per-step small kernels ----------------
__global__ __launch_bounds__(256) void k_gates() {
    int idx = blockIdx.x * blockDim.x + threadIdx.x;
    if (idx >= BQ * HQ) return;
    int b = idx >> 10;
    int u = idx & 1023;
    long long off = (long long)b * G4 + u * 4;
    float4 p0 = *(const float4*)&sc_g4[off];
    float4 p1 = *(const float4*)&sc_g4[(long long)BQ * G4 + off];
    float4 p2 = *(const float4*)&sc_g4[(long long)2 * BQ * G4 + off];
    float4 p3 = *(const float4*)&sc_g4[(long long)3 * BQ * G4 + off];
    float4 bg = *(const float4*)&sc_bg[u * 4];
    float i_ = p0.x + p1.x + p2.x + p3.x + bg.x;
    float f_ = p0.y + p1.y + p2.y + p3.y + bg.y;
    float g_ = p0.z + p1.z + p2.z + p3.z + bg.z;
    float o_ = p0.w + p1.w + p2.w + p3.w + bg.w;
    float c = sigmoidf_(f_) * sc_c[idx] + sigmoidf_(i_) * tanhf(g_);
    sc_c[idx] = c;
    float hv = sigmoidf_(o_) * tanhf(c);
    sc_h[idx] = hv;
    __nv_bfloat16 h;
    __nv_bfloat16 l;
    bsplit(hv, &h, &l);
    sc_AH[b * KR + WQ + u] = h;
    sc_AL[b * KR + WQ + u] = l;
}

__global__ __launch_bounds__(512) void k_softmax512() {
    __shared__ float sh[16];
    __shared__ float bcv;
    int q = blockIdx.x;
    int tid = threadIdx.x;
    int lane = tid & 31;
    int wid = tid >> 5;
    float beta = sc_beta[q];
    float gamma = sc_gamma[q];
    const float* row = sc_sim + (long long)q * NQ;
    float v[32];
    float mx = -1e30f;
    #pragma unroll
    for (int i = 0; i < 32; i++) { v[i] = row[tid + i * 512]; mx = fmaxf(mx, v[i]); }
    #pragma unroll
    for (int o = 16; o; o >>= 1) mx = fmaxf(mx, __shfl_xor_sync(0xffffffffu, mx, o));
    if (lane == 0) sh[wid] = mx;
    __syncthreads();
    if (tid == 0) {
        float m = sh[0];
        #pragma unroll
        for (int i = 1; i < 16; i++) m = fmaxf(m, sh[i]);
        bcv = m;
    }
    __syncthreads();
    mx = bcv;
    float s = 0.f;
    #pragma unroll
    for (int i = 0; i < 32; i++) { v[i] = __expf(beta * (v[i] - mx)); s += v[i]; }
    __syncthreads();
    #pragma unroll
    for (int o = 16; o; o >>= 1) s += __shfl_xor_sync(0xffffffffu, s, o);
    if (lane == 0) sh[wid] = s;
    __syncthreads();
    if (tid == 0) {
        float t = 0.f;
        #pragma unroll
        for (int i = 0; i < 16; i++) t += sh[i];
        bcv = 1.0f / t;
    }
    __syncthreads();
    float inv = bcv;
    if (q < 128) {
        float* rw = sc_rw + (long long)q * NQ;
        __nv_bfloat16* rh = sc_rwH + (long long)q * NQ;
        __nv_bfloat16* rl = sc_rwL + (long long)q * NQ;
        #pragma unroll
        for (int i = 0; i < 32; i++) {
            int n = tid + i * 512;
            float nv = gamma * (v[i] * inv) + (1.0f - gamma) * rw[n];
            rw[n] = nv;
            __nv_bfloat16 h;
            __nv_bfloat16 l;
            bsplit(nv, &h, &l);
            rh[n] = h;
            rl[n] = l;
        }
    } else {
        __nv_bfloat16* wh = sc_wwH + (long long)(q - 128) * NQ;
        __nv_bfloat16* wl = sc_wwL + (long long)(q - 128) * NQ;
        float u = (1.0f - gamma) * (1.0f / (float)NQ);
        #pragma unroll
        for (int i = 0; i < 32; i++) {
            int n = tid + i * 512;
            float nv = gamma * (v[i] * inv) + u;
            __nv_bfloat16 h;
            __nv_bfloat16 l;
            bsplit(nv, &h, &l);
            wh[n] = h;
            wl[n] = l;
        }
    }
}

// ---------------- memupd + rv via bf16 MMA ----------------
#define MU_STR    136
#define MU_TILE   34816
#define MU_TOTAL  208896
#define MU_RWHOFF 67584
#define MU_RWLOFF 102400
#define MU_MEMHOFF 137216
#define MU_MEMLOFF 172032

__global__ __launch_bounds__(256) void k_memupd_rv() {
    extern __shared__ char dsm[];
    __shared__ float rowsq[128][2];
    __shared__ float sInv[128];
    int tid = threadIdx.x;
    int w = tid >> 5;
    int lane = tid & 31;
    int n0 = blockIdx.x * 128;

    for (int u = tid; u < 12288; u += 256) {
        int arr = u >> 11;
        int rem = u & 2047;
        int row = rem >> 4;
        int unit = rem & 15;
        unsigned dst = sptr(dsm + arr * MU_TILE + row * (MU_STR * 2) + unit * 16);
        const __nv_bfloat16* srcb;
        if (arr == 0)      srcb = sc_wwH + (long long)row * NQ + n0 + unit * 8;
        else if (arr == 1) srcb = sc_wwL + (long long)row * NQ + n0 + unit * 8;
        else if (arr == 2) srcb = sc_erH + row * WQ + unit * 8;
        else if (arr == 3) srcb = sc_erL + row * WQ + unit * 8;
        else if (arr == 4) srcb = sc_adH + row * WQ + unit * 8;
        else               srcb = sc_adL + row * WQ + unit * 8;
        cp16(dst, srcb);
    }
    cp_commit();
    cp_wait0();
    __syncthreads();

    __nv_bfloat16* WWH = (__nv_bfloat16*)(dsm);
    __nv_bfloat16* WWL = (__nv_bfloat16*)(dsm + MU_TILE);
    __nv_bfloat16* ERH = (__nv_bfloat16*)(dsm + 2 * MU_TILE);
    __nv_bfloat16* ERL = (__nv_bfloat16*)(dsm + 3 * MU_TILE);
    __nv_bfloat16* ADH = (__nv_bfloat16*)(dsm + 4 * MU_TILE);
    __nv_bfloat16* ADL = (__nv_bfloat16*)(dsm + 5 * MU_TILE);

    int mBase = (w >> 2) * 64;
    int nBase = (w & 3) * 32;
    float accE[4][4][4] = {};
    float accA[4][4][4] = {};
    for (int kk = 0; kk < 8; kk++) {
        unsigned ah[4][4];
        unsigned al[4][4];
        int g = lane >> 3;
        int arow = kk * 16 + (g >> 1) * 8 + (lane & 7);
        #pragma unroll
        for (int mt = 0; mt < 4; mt++) {
            int acol = mBase + mt * 16 + (g & 1) * 8;
            ldm_x4t(ah[mt], sptr(WWH + arow * MU_STR + acol));
            ldm_x4t(al[mt], sptr(WWL + arow * MU_STR + acol));
        }
        int brow = kk * 16 + (lane & 15);
        #pragma unroll
        for (int nt = 0; nt < 4; nt++) {
            int bcol = nBase + nt * 8;
            unsigned ebh[2];
            unsigned ebl[2];
            unsigned abh[2];
            unsigned abl[2];
            ldm_x2t(ebh, sptr(ERH + brow * MU_STR + bcol));
            ldm_x2t(ebl, sptr(ERL + brow * MU_STR + bcol));
            ldm_x2t(abh, sptr(ADH + brow * MU_STR + bcol));
            ldm_x2t(abl, sptr(ADL + brow * MU_STR + bcol));
            #pragma unroll
            for (int mt = 0; mt < 4; mt++) {
                mma_bf16(accE[mt][nt], ah[mt], ebh);
                mma_bf16(accE[mt][nt], ah[mt], ebl);
                mma_bf16(accE[mt][nt], al[mt], ebh);
                mma_bf16(accA[mt][nt], ah[mt], abh);
                mma_bf16(accA[mt][nt], ah[mt], abl);
                mma_bf16(accA[mt][nt], al[mt], abh);
            }
        }
    }
    __syncthreads();

    for (int u = tid; u < 4096; u += 256) {
        int arr = u >> 11;
        int rem = u & 2047;
        int row = rem >> 4;
        int unit = rem & 15;
        unsigned dst = sptr(dsm + (arr ? MU_RWLOFF : MU_RWHOFF) + row * (MU_STR * 2) + unit * 16);
        const __nv_bfloat16* srcb = (arr ? sc_rwL : sc_rwH) + (long long)row * NQ + n0 + unit * 8;
        cp16(dst, srcb);
    }
    cp_commit();

    float (*mns)[132] = (float(*)[132])dsm;
    #pragma unroll
    for (int mt = 0; mt < 4; mt++) {
        #pragma unroll
        for (int half = 0; half < 2; half++) {
            int r = mBase + mt * 16 + (lane >> 2) + half * 8;
            #pragma unroll
            for (int nt = 0; nt < 4; nt++) {
                int col = nBase + nt * 8 + (lane & 3) * 2;
                long long gi = (long long)(n0 + r) * WQ + col;
                float2 mv = *(float2*)&sc_mem[gi];
                float e0 = accE[mt][nt][half * 2 + 0];
                float e1 = accE[mt][nt][half * 2 + 1];
                float a0 = accA[mt][nt][half * 2 + 0];
                float a1 = accA[mt][nt][half * 2 + 1];
                float r0 = mv.x * (1.0f - e0) + a0;
                float r1 = mv.y * (1.0f - e1) + a1;
                *(float2*)&sc_mem[gi] = make_float2(r0, r1);
                mns[r][col] = r0;
                mns[r][col + 1] = r1;
            }
        }
    }
    __syncthreads();

    {
        int r = tid >> 1;
        int half = tid & 1;
        float s = 0.f;
        #pragma unroll
        for (int t = 0; t < 64; t += 4) {
            float4 vv = *(float4*)&mns[r][half * 64 + t];
            s += vv.x * vv.x + vv.y * vv.y + vv.z * vv.z + vv.w * vv.w;
        }
        rowsq[r][half] = s;
    }
    __syncthreads();
    if (tid < 128) {
        sInv[tid] = 1.0f / fmaxf(sqrtf(rowsq[tid][0] + rowsq[tid][1]), 1e-12f);
    }
    __syncthreads();

    __nv_bfloat16* MEMH = (__nv_bfloat16*)(dsm + MU_MEMHOFF);
    __nv_bfloat16* MEML = (__nv_bfloat16*)(dsm + MU_MEMLOFF);
    for (int i = tid; i < 16384; i += 256) {
        int r = i >> 7;
        int c = i & 127;
        float v = mns[r][c];
        __nv_bfloat16 h;
        __nv_bfloat16 l;
        bsplit(v, &h, &l);
        MEMH[r * MU_STR + c] = h;
        MEML[r * MU_STR + c] = l;
        bsplit(v * sInv[r], &h, &l);
        long long o = (long long)(n0 + r) * WQ + c;
        sc_memnH[o] = h;
        sc_memnL[o] = l;
    }
    cp_wait0();
    __syncthreads();

    __nv_bfloat16* RWH = (__nv_bfloat16*)(dsm + MU_RWHOFF);
    __nv_bfloat16* RWL = (__nv_bfloat16*)(dsm + MU_RWLOFF);
    int mB2 = (w >> 1) * 32;
    int nB2 = (w & 1) * 64;
    float racc[2][8][4] = {};
    for (int kk = 0; kk < 8; kk++) {
        unsigned ah2[2][4];
        unsigned al2[2][4];
        #pragma unroll
        for (int mt = 0; mt < 2; mt++) {
            int ar = mB2 + mt * 16 + (lane & 15);
            int acol = kk * 16 + (lane >> 4) * 8;
            ldm_x4(ah2[mt], sptr(RWH + ar * MU_STR + acol));
            ldm_x4(al2[mt], sptr(RWL + ar * MU_STR + acol));
        }
        int brow = kk * 16 + (lane & 15);
        #pragma unroll
        for (int nt = 0; nt < 8; nt++) {
            int bcol = nB2 + nt * 8;
            unsigned bh[2];
            unsigned bl[2];
            ldm_x2t(bh, sptr(MEMH + brow * MU_STR + bcol));
            ldm_x2t(bl, sptr(MEML + brow * MU_STR + bcol));
            #pragma unroll
            for (int mt = 0; mt < 2; mt++) {
                mma_bf16(racc[mt][nt], ah2[mt], bh);
                mma_bf16(racc[mt][nt], ah2[mt], bl);
                mma_bf16(racc[mt][nt], al2[mt], bh);
            }
        }
    }
    float* dst = sc_rvpart + (long long)blockIdx.x * BQ * WQ;
    #pragma unroll
    for (int mt = 0; mt < 2; mt++) {
        int b = mB2 + mt * 16 + (lane >> 2);
        #pragma unroll
        for (int nt = 0; nt < 8; nt++) {
            int col = nB2 + nt * 8 + (lane & 3) * 2;
            *(float2*)&dst[b * WQ + col] = make_float2(racc[mt][nt][0], racc[mt][nt][1]);
            *(float2*)&dst[(b + 8) * WQ + col] = make_float2(racc[mt][nt][2], racc[mt][nt][3]);
        }
    }
}

__global__ __launch_bounds__(256) void k_rvreduce() {
    __shared__ float4 red[32][8];
    int tid = threadIdx.x;
    int outIdx = blockIdx.x * 32 + (tid >> 3);
    int sub = tid & 7;
    const float4* p = (const float4*)sc_rvpart;
    float4 s = make_float4(0.f, 0.f, 0.f, 0.f);
    #pragma unroll 4
    for (int i = 0; i < 16; i++) {
        float4 t = p[(long long)(sub + i * 8) * 4096 + outIdx];
        s.x += t.x; s.y += t.y; s.z += t.z; s.w += t.w;
    }
    red[tid >> 3][sub] = s;
    __syncthreads();
    if (sub == 0) {
        float4 a = make_float4(0.f, 0.f, 0.f, 0.f);
        #pragma unroll
        for (int i = 0; i < 8; i++) {
            float4 t = red[tid >> 3][i];
            a.x += t.x; a.y += t.y; a.z += t.z; a.w += t.w;
        }
        int b = outIdx >> 5;
        int c0 = (outIdx & 31) * 4;
        __nv_bfloat16 h0, l0, h1, l1, h2, l2, h3, l3;
        bsplit(a.x, &h0, &l0);
        bsplit(a.y, &h1, &l1);
        bsplit(a.z, &h2, &l2);
        bsplit(a.w, &h3, &l3);
        int o = b * KR + c0;
        st_bf2(&sc_AH[o], h0, h1);
        st_bf2(&sc_AH[o + 2], h2, h3);
        st_bf2(&sc_AL[o], l0, l1);
        st_bf2(&sc_AL[o + 2], l2, l3);
    }
}

// ---------------- host launcher ----------------
extern "C" void kernel_launch(void* const* d_in, const int* in_sizes, int n_in,
                              void* d_out, int out_size) {
    const float* x = (const float*)d_in[0];
    const float* memory = (const float*)d_in[1];
    const float* Wih = (const float*)d_in[2];
    const float* Whh = (const float*)d_in[3];
    const float* bih = (const float*)d_in[4];
    const float* bhh = (const float*)d_in[5];
    const float* Wout = (const float*)d_in[6];
    const float* bout = (const float*)d_in[7];
    const float* rkW = (const float*)d_in[8];
    const float* rkb = (const float*)d_in[9];
    const float* rbW = (const float*)d_in[10];
    const float* rbb = (const float*)d_in[11];
    const float* rgW = (const float*)d_in[12];
    const float* rgb = (const float*)d_in[13];
    const float* wkW = (const float*)d_in[14];
    const float* wkb = (const float*)d_in[15];
    const float* wbW = (const float*)d_in[16];
    const float* wbb = (const float*)d_in[17];
    const float* wgW = (const float*)d_in[18];
    const float* wgb = (const float*)d_in[19];
    const float* erW = (const float*)d_in[20];
    const float* erb = (const float*)d_in[21];
    const float* adW = (const float*)d_in[22];
    const float* adb = (const float*)d_in[23];
    const float* pW = (const float*)d_in[24];
    const float* pb = (const float*)d_in[25];
    float* out = (float*)d_out;

    cudaFuncSetAttribute(k_lstm_mma, cudaFuncAttributeMaxDynamicSharedMemorySize, 2 * L_BUFB);
    cudaFuncSetAttribute(k_homix, cudaFuncAttributeMaxDynamicSharedMemorySize, 2 * L_BUFB);
    cudaFuncSetAttribute(k_sim_mma, cudaFuncAttributeMaxDynamicSharedMemorySize, 139264);
    cudaFuncSetAttribute(k_memupd_rv, cudaFuncAttributeMaxDynamicSharedMemorySize, MU_TOTAL);

    long long setup_total = (long long)G4 * K1 + G4 + (long long)CP * HQ + (long long)HRP * CP;
    k_setup_w<<<(int)((setup_total + 255) / 256), 256>>>(Wih, Whh, bih, bhh, Wout,
                                                         rkW, rbW, rgW, wkW, wbW, wgW, erW, adW);
    long long sx_total = (long long)SQ * BQ * INQ + 2LL * (HOWP - HOW) * HQ;
    k_setup_x<<<(int)((sx_total + 255) / 256), 256>>>(x);
    k_initmem<<<2048 + 17984, 256>>>(memory);
    k_biases<<<HOW, 128>>>(bout, pW, pb, rkW, rbW, rgW, wkW, wbW, wgW, erW, adW,
                           rkb, rbb, rgb, wkb, wbb, wgb, erb, adb);
    k_fold<<<dim3(HQ / 32, 34), 256>>>(pW, Wout);

    // step 0 LSTM slices (xh + rv)
    k_lstm_mma<<<dim3(G4 / 128, 1, 3), 256, 2 * L_BUFB>>>(0, 0);
    k_lstm_mma<<<dim3(G4 / 128, 1, 1), 256, 2 * L_BUFB>>>(0, 1);

    for (int s = 0; s < SQ; s++) {
        k_gates<<<(BQ * HQ + 255) / 256, 256>>>();
        // merged: ho(s) + lstm-xh(s+1) in one launch (intra-kernel overlap)
        k_homix<<<168, 256, 2 * L_BUFB>>>(s + 1, (s + 1 < SQ) ? 1 : 0);
        k_hored<<<BQ, 128>>>(out, s);
        k_sim_mma<<<dim3(NQ / 128, 2), 256, 139264>>>();
        k_softmax512<<<2 * BQ, 512>>>();
        k_memupd_rv<<<NQ / 128, 256, MU_TOTAL>>>();
        k_rvreduce<<<128, 256>>>();
        if (s + 1 < SQ) {
            k_lstm_mma<<<dim3(G4 / 128, 1, 1), 256, 2 * L_BUFB>>>(s + 1, 1);
        }
    }
}

// round 16
// speedup vs baseline: 1.2104x; 1.2104x over previous
#include <cuda_runtime.h>
#include <cuda_bf16.h>
#include <math.h>

#define BQ   128
#define SQ   32
#define INQ  512
#define HQ   1024
#define OUTQ 512
#define NQ   16384
#define WQ   128
#define CQ   899
#define CP   960
#define K1   1664
#define KR   1152
#define G4   4096
#define HRP  576
#define HOW  1088
#define HOWP 1152
#define NCHUNK 128
#define NZ   4
#define KSLC 416

// ---------------- device globals ----------------
__device__ float sc_mem[NQ * WQ];
__device__ __nv_bfloat16 sc_WfH[(long long)G4 * K1];
__device__ __nv_bfloat16 sc_WfL[(long long)G4 * K1];
__device__ __nv_bfloat16 sc_xH[(long long)SQ * BQ * INQ];
__device__ __nv_bfloat16 sc_xL[(long long)SQ * BQ * INQ];
__device__ float sc_bg[G4];
__device__ float sc_WoutP[CP * HQ];
__device__ float sc_HW[HRP * CP];
__device__ __nv_bfloat16 sc_HOWH[(long long)HOWP * HQ];
__device__ __nv_bfloat16 sc_HOWL[(long long)HOWP * HQ];
__device__ float sc_HOb[HOW];
__device__ float sc_g4[NZ * BQ * G4];
__device__ float sc_ho8[8 * BQ * HOWP];
__device__ float sc_h[BQ * HQ];
__device__ float sc_c[BQ * HQ];
__device__ __nv_bfloat16 sc_AH[BQ * KR];
__device__ __nv_bfloat16 sc_AL[BQ * KR];
__device__ float sc_rw[BQ * NQ];
__device__ __nv_bfloat16 sc_rwH[(long long)BQ * NQ];
__device__ __nv_bfloat16 sc_rwL[(long long)BQ * NQ];
__device__ __nv_bfloat16 sc_wwH[(long long)BQ * NQ];
__device__ __nv_bfloat16 sc_wwL[(long long)BQ * NQ];
__device__ __nv_bfloat16 sc_keysH[2 * BQ * WQ];
__device__ __nv_bfloat16 sc_keysL[2 * BQ * WQ];
__device__ __nv_bfloat16 sc_memnH[NQ * WQ];
__device__ __nv_bfloat16 sc_memnL[NQ * WQ];
__device__ __nv_bfloat16 sc_erH[BQ * WQ];
__device__ __nv_bfloat16 sc_erL[BQ * WQ];
__device__ __nv_bfloat16 sc_adH[BQ * WQ];
__device__ __nv_bfloat16 sc_adL[BQ * WQ];
__device__ float sc_beta[2 * BQ];
__device__ float sc_gamma[2 * BQ];
__device__ float sc_sim[2 * BQ * NQ];
__device__ float sc_rvpart[NCHUNK * BQ * WQ];

// ---------------- helpers ----------------
__device__ __forceinline__ float sigmoidf_(float x) { return 1.0f / (1.0f + expf(-x)); }
__device__ __forceinline__ float softplusf_(float x) { return x > 20.0f ? x : log1pf(expf(x)); }

__device__ __forceinline__ void bsplit(float v, __nv_bfloat16* h, __nv_bfloat16* l) {
    __nv_bfloat16 hi = __float2bfloat16(v);
    *h = hi;
    *l = __float2bfloat16(v - __bfloat162float(hi));
}

__device__ __forceinline__ void st_bf2(__nv_bfloat16* p, __nv_bfloat16 a, __nv_bfloat16 b) {
    __nv_bfloat162 t;
    t.x = a;
    t.y = b;
    *(__nv_bfloat162*)p = t;
}

__device__ __forceinline__ unsigned sptr(const void* p) {
    return (unsigned)__cvta_generic_to_shared(p);
}

__device__ __forceinline__ void ldm_x4(unsigned* r, unsigned a) {
    asm volatile("ldmatrix.sync.aligned.m8n8.x4.shared.b16 {%0,%1,%2,%3}, [%4];"
        : "=r"(r[0]), "=r"(r[1]), "=r"(r[2]), "=r"(r[3]) : "r"(a));
}

__device__ __forceinline__ void ldm_x2(unsigned* r, unsigned a) {
    asm volatile("ldmatrix.sync.aligned.m8n8.x2.shared.b16 {%0,%1}, [%2];"
        : "=r"(r[0]), "=r"(r[1]) : "r"(a));
}

__device__ __forceinline__ void ldm_x4t(unsigned* r, unsigned a) {
    asm volatile("ldmatrix.sync.aligned.m8n8.x4.trans.shared.b16 {%0,%1,%2,%3}, [%4];"
        : "=r"(r[0]), "=r"(r[1]), "=r"(r[2]), "=r"(r[3]) : "r"(a));
}

__device__ __forceinline__ void ldm_x2t(unsigned* r, unsigned a) {
    asm volatile("ldmatrix.sync.aligned.m8n8.x2.trans.shared.b16 {%0,%1}, [%2];"
        : "=r"(r[0]), "=r"(r[1]) : "r"(a));
}

__device__ __forceinline__ void mma_bf16(float* d, const unsigned* a, const unsigned* b) {
    asm volatile("mma.sync.aligned.m16n8k16.row.col.f32.bf16.bf16.f32 "
        "{%0,%1,%2,%3}, {%4,%5,%6,%7}, {%8,%9}, {%0,%1,%2,%3};"
        : "+f"(d[0]), "+f"(d[1]), "+f"(d[2]), "+f"(d[3])
        : "r"(a[0]), "r"(a[1]), "r"(a[2]), "r"(a[3]), "r"(b[0]), "r"(b[1]));
}

__device__ __forceinline__ void cp16(unsigned dst, const void* src) {
    asm volatile("cp.async.cg.shared.global [%0], [%1], 16;" :: "r"(dst), "l"(src));
}
__device__ __forceinline__ void cp_commit() { asm volatile("cp.async.commit_group;"); }
__device__ __forceinline__ void cp_wait0() { asm volatile("cp.async.wait_group 0;"); }
__device__ __forceinline__ void cp_wait1() { asm volatile("cp.async.wait_group 1;"); }

__device__ __forceinline__ float blockSum128(float v, float* sh) {
    #pragma unroll
    for (int o = 16; o; o >>= 1) v += __shfl_xor_sync(0xffffffffu, v, o);
    if ((threadIdx.x & 31) == 0) sh[threadIdx.x >> 5] = v;
    __syncthreads();
    float r = sh[0] + sh[1] + sh[2] + sh[3];
    __syncthreads();
    return r;
}

__device__ __forceinline__ float hw_elem(int r, int k,
    const float* rkW, const float* rbW, const float* rgW,
    const float* wkW, const float* wbW, const float* wgW,
    const float* erW, const float* adW) {
    if (k >= CQ || r >= 516) return 0.0f;
    if (r < 128) return rkW[r * CQ + k];
    if (r == 128) return rbW[k];
    if (r == 129) return rgW[k];
    if (r < 258) return wkW[(r - 130) * CQ + k];
    if (r == 258) return wbW[k];
    if (r == 259) return wgW[k];
    if (r < 388) return erW[(r - 260) * CQ + k];
    return adW[(r - 388) * CQ + k];
}

__device__ __forceinline__ float hb_elem(int r,
    const float* rkb, const float* rbb, const float* rgb,
    const float* wkb, const float* wbb, const float* wgb,
    const float* erb, const float* adb) {
    if (r < 128) return rkb[r];
    if (r == 128) return rbb[0];
    if (r == 129) return rgb[0];
    if (r < 258) return wkb[r - 130];
    if (r == 258) return wbb[0];
    if (r == 259) return wgb[0];
    if (r < 388) return erb[r - 260];
    if (r < 516) return adb[r - 388];
    return 0.0f;
}

// ---------------- prologue ----------------
__global__ void k_setup_w(const float* __restrict__ Wih, const float* __restrict__ Whh,
                          const float* __restrict__ bih, const float* __restrict__ bhh,
                          const float* __restrict__ Wout,
                          const float* rkW, const float* rbW, const float* rgW,
                          const float* wkW, const float* wbW, const float* wgW,
                          const float* erW, const float* adW) {
    long long i = (long long)blockIdx.x * blockDim.x + threadIdx.x;
    const long long NW = (long long)G4 * K1;
    const long long ND = (long long)CP * HQ;
    const long long NE = (long long)HRP * CP;
    if (i < NW) {
        int r = (int)(i / K1);
        int k = (int)(i % K1);
        int src = (r & 3) * HQ + (r >> 2);
        float v = (k < INQ + WQ) ? Wih[src * (INQ + WQ) + k] : Whh[src * HQ + (k - INQ - WQ)];
        __nv_bfloat16 h, l;
        bsplit(v, &h, &l);
        sc_WfH[i] = h;
        sc_WfL[i] = l;
        return;
    }
    i -= NW;
    if (i < G4) {
        int r = (int)i;
        int src = (r & 3) * HQ + (r >> 2);
        sc_bg[r] = bih[src] + bhh[src];
        return;
    }
    i -= G4;
    if (i < ND) {
        int r = (int)(i / HQ);
        sc_WoutP[i] = (r < CQ) ? Wout[(long long)r * HQ + (i % HQ)] : 0.0f;
        return;
    }
    i -= ND;
    if (i < NE) {
        int r = (int)(i / CP);
        int k = (int)(i % CP);
        sc_HW[i] = hw_elem(r, k, rkW, rbW, rgW, wkW, wbW, wgW, erW, adW);
        return;
    }
}

__global__ void k_setup_x(const float* __restrict__ x) {
    long long i = (long long)blockIdx.x * blockDim.x + threadIdx.x;
    const long long NX = (long long)SQ * BQ * INQ;
    if (i < NX) {
        int k = (int)(i % INQ);
        long long sb = i / INQ;
        int b = (int)(sb % BQ);
        int s = (int)(sb / BQ);
        float v = x[((long long)b * SQ + s) * INQ + k];
        __nv_bfloat16 h, l;
        bsplit(v, &h, &l);
        sc_xH[i] = h;
        sc_xL[i] = l;
        return;
    }
    i -= NX;
    const long long NP = (long long)(HOWP - HOW) * HQ;
    if (i < 2 * NP) {
        __nv_bfloat16 z = __float2bfloat16(0.0f);
        long long j = (i < NP) ? i : (i - NP);
        long long idx = (long long)(HOW + (int)(j / HQ)) * HQ + (int)(j % HQ);
        if (i < NP) sc_HOWH[idx] = z;
        else        sc_HOWL[idx] = z;
    }
}

__global__ __launch_bounds__(256) void k_initmem(const float* __restrict__ memory) {
    if (blockIdx.x < 2048) {
        int row = blockIdx.x * 8 + (threadIdx.x >> 5);
        int lane = threadIdx.x & 31;
        const float* src = memory + (long long)row * WQ;
        float v[4];
        float s = 0.f;
        #pragma unroll
        for (int i = 0; i < 4; i++) { v[i] = src[lane + 32 * i]; s += v[i] * v[i]; }
        #pragma unroll
        for (int o = 16; o; o >>= 1) s += __shfl_xor_sync(0xffffffffu, s, o);
        float inv = 1.0f / fmaxf(sqrtf(s), 1e-12f);
        #pragma unroll
        for (int i = 0; i < 4; i++) {
            long long o = (long long)row * WQ + lane + 32 * i;
            sc_mem[o] = v[i];
            __nv_bfloat16 h, l;
            bsplit(v[i] * inv, &h, &l);
            sc_memnH[o] = h;
            sc_memnL[o] = l;
        }
    } else {
        long long base = (long long)(blockIdx.x - 2048) * 256 + threadIdx.x;
        if (base < (long long)BQ * NQ) { sc_rw[base] = 1.0f / (float)NQ; return; }
        base -= (long long)BQ * NQ;
        if (base < (long long)BQ * NQ / 2) { ((unsigned*)sc_rwH)[base] = 0x38803880u; return; }
        base -= (long long)BQ * NQ / 2;
        if (base < (long long)BQ * NQ / 2) { ((unsigned*)sc_rwL)[base] = 0u; return; }
        base -= (long long)BQ * NQ / 2;
        if (base < BQ * HQ) { sc_h[base] = 0.0f; return; }
        base -= BQ * HQ;
        if (base < BQ * HQ) { sc_c[base] = 0.0f; return; }
        base -= BQ * HQ;
        if (base < BQ * KR / 2) { ((unsigned*)sc_AH)[base] = 0u; return; }
        base -= BQ * KR / 2;
        if (base < BQ * KR / 2) { ((unsigned*)sc_AL)[base] = 0u; return; }
    }
}

__global__ __launch_bounds__(128) void k_biases(const float* bout, const float* pW, const float* pb,
    const float* rkW, const float* rbW, const float* rgW,
    const float* wkW, const float* wbW, const float* wgW,
    const float* erW, const float* adW,
    const float* rkb, const float* rbb, const float* rgb,
    const float* wkb, const float* wbb, const float* wgb,
    const float* erb, const float* adb) {
    __shared__ float sh[4];
    int r = blockIdx.x;
    int t = threadIdx.x;
    float s = 0.f;
    if (r < HRP) {
        for (int c = t; c < CQ; c += 128)
            s += hw_elem(r, c, rkW, rbW, rgW, wkW, wbW, wgW, erW, adW) * bout[c];
        s = blockSum128(s, sh);
        if (t == 0) sc_HOb[r] = s + hb_elem(r, rkb, rbb, rgb, wkb, wbb, wgb, erb, adb);
    } else {
        int o = r - HRP;
        for (int c = t; c < OUTQ; c += 128) s += pW[o * OUTQ + c] * bout[c];
        s = blockSum128(s, sh);
        if (t == 0) sc_HOb[r] = s + pb[o];
    }
}

__global__ __launch_bounds__(256) void k_fold(const float* __restrict__ pW,
                                              const float* __restrict__ Wout) {
    __shared__ float As[32][36];
    __shared__ float Bs[32][36];
    int tid = threadIdx.x;
    int n0 = blockIdx.x * 32;
    int second = (blockIdx.y >= 18) ? 1 : 0;
    int m0 = second ? (blockIdx.y - 18) * 32 : blockIdx.y * 32;
    const float* A = second ? pW : sc_HW;
    const float* B = second ? Wout : sc_WoutP;
    int lda = second ? OUTQ : CP;
    int K = second ? OUTQ : CP;
    int dstRow = second ? HRP : 0;
    int rowL = tid >> 3;
    int k4 = (tid & 7) * 4;
    int tm = tid & 7;
    int tn = tid >> 3;
    float acc[4] = {};
    for (int k0 = 0; k0 < K; k0 += 32) {
        float4 a = *(const float4*)(A + (long long)(m0 + rowL) * lda + k0 + k4);
        float4 b = *(const float4*)(B + (long long)(k0 + rowL) * HQ + n0 + k4);
        As[rowL][k4 + 0] = a.x; As[rowL][k4 + 1] = a.y; As[rowL][k4 + 2] = a.z; As[rowL][k4 + 3] = a.w;
        Bs[rowL][k4 + 0] = b.x; Bs[rowL][k4 + 1] = b.y; Bs[rowL][k4 + 2] = b.z; Bs[rowL][k4 + 3] = b.w;
        __syncthreads();
        #pragma unroll
        for (int k = 0; k < 32; k++) {
            float bv = Bs[k][tn];
            #pragma unroll
            for (int i = 0; i < 4; i++) acc[i] = fmaf(As[tm * 4 + i][k], bv, acc[i]);
        }
        __syncthreads();
    }
    #pragma unroll
    for (int i = 0; i < 4; i++) {
        long long idx = (long long)(dstRow + m0 + tm * 4 + i) * HQ + n0 + tn;
        __nv_bfloat16 h;
        __nv_bfloat16 l;
        bsplit(acc[i], &h, &l);
        sc_HOWH[idx] = h;
        sc_HOWL[idx] = l;
    }
}

// ---------------- LSTM full GEMM ----------------
#define L_ROWHW 40
#define L_SEGB  (128 * L_ROWHW * 2)
#define L_BUFB  (4 * L_SEGB)

__device__ __forceinline__ void lstm_stage(char* dsm, int buf, int c, int n0, int kbase, int s, int tid) {
    for (int u = tid; u < 2048; u += 256) {
        int seg = u >> 9;
        int rem = u & 511;
        int row = rem >> 2;
        int unit = rem & 3;
        unsigned dst = sptr(dsm + buf * L_BUFB + seg * L_SEGB + row * (L_ROWHW * 2) + unit * 16);
        int kk = kbase + c * 32 + unit * 8;
        const char* src;
        if (seg < 2) {
            if (kk < INQ) {
                const __nv_bfloat16* base = (seg == 0) ? sc_xH : sc_xL;
                src = (const char*)(base + ((long long)s * BQ + row) * INQ + kk);
            } else {
                const __nv_bfloat16* base = (seg == 0) ? sc_AH : sc_AL;
                src = (const char*)(base + (long long)row * KR + (kk - INQ));
            }
        } else {
            const __nv_bfloat16* base = (seg == 2) ? sc_WfH : sc_WfL;
            src = (const char*)(base + (long long)(n0 + row) * K1 + kk);
        }
        cp16(dst, src);
    }
    cp_commit();
}

__global__ __launch_bounds__(256) void k_lstm_mma(int s) {
    extern __shared__ char dsm[];
    int tid = threadIdx.x;
    int w = tid >> 5;
    int lane = tid & 31;
    int n0 = blockIdx.x * 128;
    int z = blockIdx.z;
    int kbase = z * KSLC;
    int mBase = (w >> 2) * 64;
    int nBase = (w & 3) * 32;
    float acc[4][4][4] = {};
    lstm_stage(dsm, 0, 0, n0, kbase, s, tid);
    for (int c = 0; c < 13; c++) {
        if (c < 12) {
            lstm_stage(dsm, (c + 1) & 1, c + 1, n0, kbase, s, tid);
            cp_wait1();
        } else {
            cp_wait0();
        }
        __syncthreads();
        char* B0 = dsm + (c & 1) * L_BUFB;
        __nv_bfloat16* AHs = (__nv_bfloat16*)B0;
        __nv_bfloat16* ALs = (__nv_bfloat16*)(B0 + L_SEGB);
        __nv_bfloat16* BHs = (__nv_bfloat16*)(B0 + 2 * L_SEGB);
        __nv_bfloat16* BLs = (__nv_bfloat16*)(B0 + 3 * L_SEGB);
        #pragma unroll
        for (int kk = 0; kk < 2; kk++) {
            unsigned ah[4][4];
            unsigned al[4][4];
            int acol = kk * 16 + (lane >> 4) * 8;
            #pragma unroll
            for (int mt = 0; mt < 4; mt++) {
                int ar = mBase + mt * 16 + (lane & 15);
                ldm_x4(ah[mt], sptr(AHs + ar * L_ROWHW + acol));
                ldm_x4(al[mt], sptr(ALs + ar * L_ROWHW + acol));
            }
            int q = lane & 15;
            int bcol = kk * 16 + (q >> 3) * 8;
            #pragma unroll
            for (int nt = 0; nt < 4; nt++) {
                int br = nBase + nt * 8 + (q & 7);
                unsigned bh[2];
                unsigned bl[2];
                ldm_x2(bh, sptr(BHs + br * L_ROWHW + bcol));
                ldm_x2(bl, sptr(BLs + br * L_ROWHW + bcol));
                #pragma unroll
                for (int mt = 0; mt < 4; mt++) {
                    mma_bf16(acc[mt][nt], ah[mt], bh);
                    mma_bf16(acc[mt][nt], ah[mt], bl);
                    mma_bf16(acc[mt][nt], al[mt], bh);
                }
            }
        }
        __syncthreads();
    }
    float* dst = sc_g4 + (long long)z * BQ * G4;
    #pragma unroll
    for (int mt = 0; mt < 4; mt++) {
        int r = mBase + mt * 16 + (lane >> 2);
        #pragma unroll
        for (int nt = 0; nt < 4; nt++) {
            int cc = n0 + nBase + nt * 8 + (lane & 3) * 2;
            *(float2*)&dst[(long long)r * G4 + cc] = make_float2(acc[mt][nt][0], acc[mt][nt][1]);
            *(float2*)&dst[(long long)(r + 8) * G4 + cc] = make_float2(acc[mt][nt][2], acc[mt][nt][3]);
        }
    }
}

// ---------------- heads+out GEMM via bf16 MMA (split-K 8, partials) ----------------
__device__ __forceinline__ void ho_stage(char* dsm, int buf, int c, int n0, int kbase, int tid) {
    for (int u = tid; u < 2048; u += 256) {
        int seg = u >> 9;
        int rem = u & 511;
        int row = rem >> 2;
        int unit = rem & 3;
        unsigned dst = sptr(dsm + buf * L_BUFB + seg * L_SEGB + row * (L_ROWHW * 2) + unit * 16);
        int kk = kbase + c * 32 + unit * 8;
        const __nv_bfloat16* base;
        if (seg == 0)      base = sc_AH + (long long)row * KR + WQ + kk;
        else if (seg == 1) base = sc_AL + (long long)row * KR + WQ + kk;
        else if (seg == 2) base = sc_HOWH + (long long)(n0 + row) * HQ + kk;
        else               base = sc_HOWL + (long long)(n0 + row) * HQ + kk;
        cp16(dst, base);
    }
    cp_commit();
}

__global__ __launch_bounds__(256) void k_ho_mma() {
    extern __shared__ char dsm[];
    int tid = threadIdx.x;
    int w = tid >> 5;
    int lane = tid & 31;
    int n0 = blockIdx.x * 128;
    int z = blockIdx.z;
    int kbase = z * 128;
    int mBase = (w >> 2) * 64;
    int nBase = (w & 3) * 32;
    float acc[4][4][4] = {};
    ho_stage(dsm, 0, 0, n0, kbase, tid);
    for (int c = 0; c < 4; c++) {
        if (c < 3) {
            ho_stage(dsm, (c + 1) & 1, c + 1, n0, kbase, tid);
            cp_wait1();
        } else {
            cp_wait0();
        }
        __syncthreads();
        char* B0 = dsm + (c & 1) * L_BUFB;
        __nv_bfloat16* AHs = (__nv_bfloat16*)B0;
        __nv_bfloat16* ALs = (__nv_bfloat16*)(B0 + L_SEGB);
        __nv_bfloat16* BHs = (__nv_bfloat16*)(B0 + 2 * L_SEGB);
        __nv_bfloat16* BLs = (__nv_bfloat16*)(B0 + 3 * L_SEGB);
        #pragma unroll
        for (int kk = 0; kk < 2; kk++) {
            unsigned ah[4][4];
            unsigned al[4][4];
            int acol = kk * 16 + (lane >> 4) * 8;
            #pragma unroll
            for (int mt = 0; mt < 4; mt++) {
                int ar = mBase + mt * 16 + (lane & 15);
                ldm_x4(ah[mt], sptr(AHs + ar * L_ROWHW + acol));
                ldm_x4(al[mt], sptr(ALs + ar * L_ROWHW + acol));
            }
            int q = lane & 15;
            int bcol = kk * 16 + (q >> 3) * 8;
            #pragma unroll
            for (int nt = 0; nt < 4; nt++) {
                int br = nBase + nt * 8 + (q & 7);
                unsigned bh[2];
                unsigned bl[2];
                ldm_x2(bh, sptr(BHs + br * L_ROWHW + bcol));
                ldm_x2(bl, sptr(BLs + br * L_ROWHW + bcol));
                #pragma unroll
                for (int mt = 0; mt < 4; mt++) {
                    mma_bf16(acc[mt][nt], ah[mt], bh);
                    mma_bf16(acc[mt][nt], ah[mt], bl);
                    mma_bf16(acc[mt][nt], al[mt], bh);
                }
            }
        }
        __syncthreads();
    }
    float* dst = sc_ho8 + (long long)z * BQ * HOWP;
    #pragma unroll
    for (int mt = 0; mt < 4; mt++) {
        int r = mBase + mt * 16 + (lane >> 2);
        #pragma unroll
        for (int nt = 0; nt < 4; nt++) {
            int cc = n0 + nBase + nt * 8 + (lane & 3) * 2;
            *(float2*)&dst[(long long)r * HOWP + cc] = make_float2(acc[mt][nt][0], acc[mt][nt][1]);
            *(float2*)&dst[(long long)(r + 8) * HOWP + cc] = make_float2(acc[mt][nt][2], acc[mt][nt][3]);
        }
    }
}

__global__ __launch_bounds__(128) void k_hored(float* __restrict__ out, int s) {
    __shared__ float hrow[HRP];
    __shared__ float sh[4];
    int b = blockIdx.x;
    int t = threadIdx.x;
    for (int n = t; n < HOW; n += 128) {
        float v = sc_HOb[n];
        #pragma unroll
        for (int z = 0; z < 8; z++)
            v += sc_ho8[((long long)z * BQ + b) * HOWP + n];
        if (n < HRP) hrow[n] = v;
        else out[((long long)b * SQ + s) * OUTQ + (n - HRP)] = v;
    }
    __syncthreads();
    float rk = hrow[t];
    float wk = hrow[130 + t];
    float nr2 = blockSum128(rk * rk, sh);
    float nw2 = blockSum128(wk * wk, sh);
    __nv_bfloat16 h;
    __nv_bfloat16 l;
    bsplit(rk / fmaxf(sqrtf(nr2), 1e-12f), &h, &l);
    sc_keysH[b * WQ + t] = h;
    sc_keysL[b * WQ + t] = l;
    bsplit(wk / fmaxf(sqrtf(nw2), 1e-12f), &h, &l);
    sc_keysH[(128 + b) * WQ + t] = h;
    sc_keysL[(128 + b) * WQ + t] = l;
    if (t == 0) {
        sc_beta[b] = softplusf_(hrow[128]);
        sc_gamma[b] = 1.0f + softplusf_(hrow[129]);
        sc_beta[128 + b] = softplusf_(hrow[258]);
        sc_gamma[128 + b] = 1.0f + softplusf_(hrow[259]);
    }
    bsplit(sigmoidf_(hrow[260 + t]), &h, &l);
    sc_erH[b * WQ + t] = h;
    sc_erL[b * WQ + t] = l;
    bsplit(tanhf(hrow[388 + t]), &h, &l);
    sc_adH[b * WQ + t] = h;
    sc_adL[b * WQ + t] = l;
}

// ---------------- sim GEMM: single-wave (64x2 grid), A reused, B double-buffered ----------------
#define SIM_A   34816
#define SIM_B0  69632
#define SIM_BSZ 69632
#define SIM_TOT 208896

__device__ __forceinline__ void sim_stageB(char* dsm, int buf, int n0, int tid) {
    for (int u = tid; u < 4096; u += 256) {
        int seg = u >> 11;
        int rem = u & 2047;
        int row = rem >> 4;
        int unit = rem & 15;
        unsigned dst = sptr(dsm + SIM_B0 + buf * SIM_BSZ + seg * SIM_A + row * 272 + unit * 16);
        const __nv_bfloat16* src = ((seg == 0) ? sc_memnH : sc_memnL) + (long long)(n0 + row) * WQ + unit * 8;
        cp16(dst, src);
    }
}

__global__ __launch_bounds__(256, 1) void k_sim_mma() {
    extern __shared__ char dsm[];
    __nv_bfloat16* AHs = (__nv_bfloat16*)dsm;
    __nv_bfloat16* ALs = (__nv_bfloat16*)(dsm + SIM_A);
    int tid = threadIdx.x;
    int w = tid >> 5;
    int lane = tid & 31;
    int m0 = blockIdx.y * 128;
    int n00 = blockIdx.x * 256;
    // stage A (keys, reused across both n-tiles) + B0 in one group
    for (int u = tid; u < 4096; u += 256) {
        int seg = u >> 11;
        int rem = u & 2047;
        int row = rem >> 4;
        int unit = rem & 15;
        unsigned dst = sptr(dsm + seg * SIM_A + row * 272 + unit * 16);
        const __nv_bfloat16* src = ((seg == 0) ? sc_keysH : sc_keysL) + (long long)(m0 + row) * WQ + unit * 8;
        cp16(dst, src);
    }
    sim_stageB(dsm, 0, n00, tid);
    cp_commit();
    sim_stageB(dsm, 1, n00 + 128, tid);
    cp_commit();
    cp_wait1();
    __syncthreads();
    int mBase = (w >> 2) * 64;
    int nBase = (w & 3) * 32;
    #pragma unroll 1
    for (int it = 0; it < 2; it++) {
        if (it == 1) {
            cp_wait0();
            __syncthreads();
        }
        __nv_bfloat16* BHs = (__nv_bfloat16*)(dsm + SIM_B0 + it * SIM_BSZ);
        __nv_bfloat16* BLs = (__nv_bfloat16*)(dsm + SIM_B0 + it * SIM_BSZ + SIM_A);
        int n0 = n00 + it * 128;
        float acc[4][4][4] = {};
        #pragma unroll
        for (int kk = 0; kk < 8; kk++) {
            unsigned ah[4][4];
            unsigned al[4][4];
            int acol = kk * 16 + (lane >> 4) * 8;
            #pragma unroll
            for (int mt = 0; mt < 4; mt++) {
                int ar = mBase + mt * 16 + (lane & 15);
                ldm_x4(ah[mt], sptr(AHs + ar * 136 + acol));
                ldm_x4(al[mt], sptr(ALs + ar * 136 + acol));
            }
            int q = lane & 15;
            int bcol = kk * 16 + (q >> 3) * 8;
            #pragma unroll
            for (int nt = 0; nt < 4; nt++) {
                int br = nBase + nt * 8 + (q & 7);
                unsigned bh[2];
                unsigned bl[2];
                ldm_x2(bh, sptr(BHs + br * 136 + bcol));
                ldm_x2(bl, sptr(BLs + br * 136 + bcol));
                #pragma unroll
                for (int mt = 0; mt < 4; mt++) {
                    mma_bf16(acc[mt][nt], ah[mt], bh);
                    mma_bf16(acc[mt][nt], ah[mt], bl);
                    mma_bf16(acc[mt][nt], al[mt], bh);
                }
            }
        }
        #pragma unroll
        for (int mt = 0; mt < 4; mt++) {
            int r = m0 + mBase + mt * 16 + (lane >> 2);
            #pragma unroll
            for (int nt = 0; nt < 4; nt++) {
                int cc = n0 + nBase + nt * 8 + (lane & 3) * 2;
                *(float2*)&sc_sim[(long long)r * NQ + cc] = make_float2(acc[mt][nt][0], acc[mt][nt][1]);
                *(float2*)&sc_sim[(long long)(r + 8) * NQ + cc] = make_float2(acc[mt][nt][2], acc[mt][nt][3]);
            }
        }
    }
}

// ---------------- per-step small kernels ----------------
__global__ __launch_bounds__(256) void k_gates() {
    int idx = blockIdx.x * blockDim.x + threadIdx.x;
    if (idx >= BQ * HQ) return;
    int b = idx >> 10;
    int u = idx & 1023;
    long long off = (long long)b * G4 + u * 4;
    float4 p0 = *(const float4*)&sc_g4[off];
    float4 p1 = *(const float4*)&sc_g4[(long long)BQ * G4 + off];
    float4 p2 = *(const float4*)&sc_g4[(long long)2 * BQ * G4 + off];
    float4 p3 = *(const float4*)&sc_g4[(long long)3 * BQ * G4 + off];
    float4 bg = *(const float4*)&sc_bg[u * 4];
    float i_ = p0.x + p1.x + p2.x + p3.x + bg.x;
    float f_ = p0.y + p1.y + p2.y + p3.y + bg.y;
    float g_ = p0.z + p1.z + p2.z + p3.z + bg.z;
    float o_ = p0.w + p1.w + p2.w + p3.w + bg.w;
    float c = sigmoidf_(f_) * sc_c[idx] + sigmoidf_(i_) * tanhf(g_);
    sc_c[idx] = c;
    float hv = sigmoidf_(o_) * tanhf(c);
    sc_h[idx] = hv;
    __nv_bfloat16 h;
    __nv_bfloat16 l;
    bsplit(hv, &h, &l);
    sc_AH[b * KR + WQ + u] = h;
    sc_AL[b * KR + WQ + u] = l;
}

__global__ __launch_bounds__(512) void k_softmax512() {
    __shared__ float sh[16];
    __shared__ float bcv;
    int q = blockIdx.x;
    int tid = threadIdx.x;
    int lane = tid & 31;
    int wid = tid >> 5;
    float beta = sc_beta[q];
    float gamma = sc_gamma[q];
    const float* row = sc_sim + (long long)q * NQ;
    float v[32];
    float mx = -1e30f;
    #pragma unroll
    for (int i = 0; i < 32; i++) { v[i] = row[tid + i * 512]; mx = fmaxf(mx, v[i]); }
    #pragma unroll
    for (int o = 16; o; o >>= 1) mx = fmaxf(mx, __shfl_xor_sync(0xffffffffu, mx, o));
    if (lane == 0) sh[wid] = mx;
    __syncthreads();
    if (tid == 0) {
        float m = sh[0];
        #pragma unroll
        for (int i = 1; i < 16; i++) m = fmaxf(m, sh[i]);
        bcv = m;
    }
    __syncthreads();
    mx = bcv;
    float s = 0.f;
    #pragma unroll
    for (int i = 0; i < 32; i++) { v[i] = __expf(beta * (v[i] - mx)); s += v[i]; }
    __syncthreads();
    #pragma unroll
    for (int o = 16; o; o >>= 1) s += __shfl_xor_sync(0xffffffffu, s, o);
    if (lane == 0) sh[wid] = s;
    __syncthreads();
    if (tid == 0) {
        float t = 0.f;
        #pragma unroll
        for (int i = 0; i < 16; i++) t += sh[i];
        bcv = 1.0f / t;
    }
    __syncthreads();
    float inv = bcv;
    if (q < 128) {
        float* rw = sc_rw + (long long)q * NQ;
        __nv_bfloat16* rh = sc_rwH + (long long)q * NQ;
        __nv_bfloat16* rl = sc_rwL + (long long)q * NQ;
        #pragma unroll
        for (int i = 0; i < 32; i++) {
            int n = tid + i * 512;
            float nv = gamma * (v[i] * inv) + (1.0f - gamma) * rw[n];
            rw[n] = nv;
            __nv_bfloat16 h;
            __nv_bfloat16 l;
            bsplit(nv, &h, &l);
            rh[n] = h;
            rl[n] = l;
        }
    } else {
        __nv_bfloat16* wh = sc_wwH + (long long)(q - 128) * NQ;
        __nv_bfloat16* wl = sc_wwL + (long long)(q - 128) * NQ;
        float u = (1.0f - gamma) * (1.0f / (float)NQ);
        #pragma unroll
        for (int i = 0; i < 32; i++) {
            int n = tid + i * 512;
            float nv = gamma * (v[i] * inv) + u;
            __nv_bfloat16 h;
            __nv_bfloat16 l;
            bsplit(nv, &h, &l);
            wh[n] = h;
            wl[n] = l;
        }
    }
}

// ---------------- memupd + rv via bf16 MMA ----------------
#define MU_STR    136
#define MU_TILE   34816
#define MU_TOTAL  208896
#define MU_RWHOFF 67584
#define MU_RWLOFF 102400
#define MU_MEMHOFF 137216
#define MU_MEMLOFF 172032

__global__ __launch_bounds__(256) void k_memupd_rv() {
    extern __shared__ char dsm[];
    __shared__ float rowsq[128][2];
    __shared__ float sInv[128];
    int tid = threadIdx.x;
    int w = tid >> 5;
    int lane = tid & 31;
    int n0 = blockIdx.x * 128;

    for (int u = tid; u < 12288; u += 256) {
        int arr = u >> 11;
        int rem = u & 2047;
        int row = rem >> 4;
        int unit = rem & 15;
        unsigned dst = sptr(dsm + arr * MU_TILE + row * (MU_STR * 2) + unit * 16);
        const __nv_bfloat16* srcb;
        if (arr == 0)      srcb = sc_wwH + (long long)row * NQ + n0 + unit * 8;
        else if (arr == 1) srcb = sc_wwL + (long long)row * NQ + n0 + unit * 8;
        else if (arr == 2) srcb = sc_erH + row * WQ + unit * 8;
        else if (arr == 3) srcb = sc_erL + row * WQ + unit * 8;
        else if (arr == 4) srcb = sc_adH + row * WQ + unit * 8;
        else               srcb = sc_adL + row * WQ + unit * 8;
        cp16(dst, srcb);
    }
    cp_commit();
    cp_wait0();
    __syncthreads();

    __nv_bfloat16* WWH = (__nv_bfloat16*)(dsm);
    __nv_bfloat16* WWL = (__nv_bfloat16*)(dsm + MU_TILE);
    __nv_bfloat16* ERH = (__nv_bfloat16*)(dsm + 2 * MU_TILE);
    __nv_bfloat16* ERL = (__nv_bfloat16*)(dsm + 3 * MU_TILE);
    __nv_bfloat16* ADH = (__nv_bfloat16*)(dsm + 4 * MU_TILE);
    __nv_bfloat16* ADL = (__nv_bfloat16*)(dsm + 5 * MU_TILE);

    int mBase = (w >> 2) * 64;
    int nBase = (w & 3) * 32;
    float accE[4][4][4] = {};
    float accA[4][4][4] = {};
    for (int kk = 0; kk < 8; kk++) {
        unsigned ah[4][4];
        unsigned al[4][4];
        int g = lane >> 3;
        int arow = kk * 16 + (g >> 1) * 8 + (lane & 7);
        #pragma unroll
        for (int mt = 0; mt < 4; mt++) {
            int acol = mBase + mt * 16 + (g & 1) * 8;
            ldm_x4t(ah[mt], sptr(WWH + arow * MU_STR + acol));
            ldm_x4t(al[mt], sptr(WWL + arow * MU_STR + acol));
        }
        int brow = kk * 16 + (lane & 15);
        #pragma unroll
        for (int nt = 0; nt < 4; nt++) {
            int bcol = nBase + nt * 8;
            unsigned ebh[2];
            unsigned ebl[2];
            unsigned abh[2];
            unsigned abl[2];
            ldm_x2t(ebh, sptr(ERH + brow * MU_STR + bcol));
            ldm_x2t(ebl, sptr(ERL + brow * MU_STR + bcol));
            ldm_x2t(abh, sptr(ADH + brow * MU_STR + bcol));
            ldm_x2t(abl, sptr(ADL + brow * MU_STR + bcol));
            #pragma unroll
            for (int mt = 0; mt < 4; mt++) {
                mma_bf16(accE[mt][nt], ah[mt], ebh);
                mma_bf16(accE[mt][nt], ah[mt], ebl);
                mma_bf16(accE[mt][nt], al[mt], ebh);
                mma_bf16(accA[mt][nt], ah[mt], abh);
                mma_bf16(accA[mt][nt], ah[mt], abl);
                mma_bf16(accA[mt][nt], al[mt], abh);
            }
        }
    }
    __syncthreads();

    for (int u = tid; u < 4096; u += 256) {
        int arr = u >> 11;
        int rem = u & 2047;
        int row = rem >> 4;
        int unit = rem & 15;
        unsigned dst = sptr(dsm + (arr ? MU_RWLOFF : MU_RWHOFF) + row * (MU_STR * 2) + unit * 16);
        const __nv_bfloat16* srcb = (arr ? sc_rwL : sc_rwH) + (long long)row * NQ + n0 + unit * 8;
        cp16(dst, srcb);
    }
    cp_commit();

    float (*mns)[132] = (float(*)[132])dsm;
    #pragma unroll
    for (int mt = 0; mt < 4; mt++) {
        #pragma unroll
        for (int half = 0; half < 2; half++) {
            int r = mBase + mt * 16 + (lane >> 2) + half * 8;
            #pragma unroll
            for (int nt = 0; nt < 4; nt++) {
                int col = nBase + nt * 8 + (lane & 3) * 2;
                long long gi = (long long)(n0 + r) * WQ + col;
                float2 mv = *(float2*)&sc_mem[gi];
                float e0 = accE[mt][nt][half * 2 + 0];
                float e1 = accE[mt][nt][half * 2 + 1];
                float a0 = accA[mt][nt][half * 2 + 0];
                float a1 = accA[mt][nt][half * 2 + 1];
                float r0 = mv.x * (1.0f - e0) + a0;
                float r1 = mv.y * (1.0f - e1) + a1;
                *(float2*)&sc_mem[gi] = make_float2(r0, r1);
                mns[r][col] = r0;
                mns[r][col + 1] = r1;
            }
        }
    }
    __syncthreads();

    {
        int r = tid >> 1;
        int half = tid & 1;
        float s = 0.f;
        #pragma unroll
        for (int t = 0; t < 64; t += 4) {
            float4 vv = *(float4*)&mns[r][half * 64 + t];
            s += vv.x * vv.x + vv.y * vv.y + vv.z * vv.z + vv.w * vv.w;
        }
        rowsq[r][half] = s;
    }
    __syncthreads();
    if (tid < 128) {
        sInv[tid] = 1.0f / fmaxf(sqrtf(rowsq[tid][0] + rowsq[tid][1]), 1e-12f);
    }
    __syncthreads();

    __nv_bfloat16* MEMH = (__nv_bfloat16*)(dsm + MU_MEMHOFF);
    __nv_bfloat16* MEML = (__nv_bfloat16*)(dsm + MU_MEMLOFF);
    for (int i = tid; i < 16384; i += 256) {
        int r = i >> 7;
        int c = i & 127;
        float v = mns[r][c];
        __nv_bfloat16 h;
        __nv_bfloat16 l;
        bsplit(v, &h, &l);
        MEMH[r * MU_STR + c] = h;
        MEML[r * MU_STR + c] = l;
        bsplit(v * sInv[r], &h, &l);
        long long o = (long long)(n0 + r) * WQ + c;
        sc_memnH[o] = h;
        sc_memnL[o] = l;
    }
    cp_wait0();
    __syncthreads();

    __nv_bfloat16* RWH = (__nv_bfloat16*)(dsm + MU_RWHOFF);
    __nv_bfloat16* RWL = (__nv_bfloat16*)(dsm + MU_RWLOFF);
    int mB2 = (w >> 1) * 32;
    int nB2 = (w & 1) * 64;
    float racc[2][8][4] = {};
    for (int kk = 0; kk < 8; kk++) {
        unsigned ah2[2][4];
        unsigned al2[2][4];
        #pragma unroll
        for (int mt = 0; mt < 2; mt++) {
            int ar = mB2 + mt * 16 + (lane & 15);
            int acol = kk * 16 + (lane >> 4) * 8;
            ldm_x4(ah2[mt], sptr(RWH + ar * MU_STR + acol));
            ldm_x4(al2[mt], sptr(RWL + ar * MU_STR + acol));
        }
        int brow = kk * 16 + (lane & 15);
        #pragma unroll
        for (int nt = 0; nt < 8; nt++) {
            int bcol = nB2 + nt * 8;
            unsigned bh[2];
            unsigned bl[2];
            ldm_x2t(bh, sptr(MEMH + brow * MU_STR + bcol));
            ldm_x2t(bl, sptr(MEML + brow * MU_STR + bcol));
            #pragma unroll
            for (int mt = 0; mt < 2; mt++) {
                mma_bf16(racc[mt][nt], ah2[mt], bh);
                mma_bf16(racc[mt][nt], ah2[mt], bl);
                mma_bf16(racc[mt][nt], al2[mt], bh);
            }
        }
    }
    float* dst = sc_rvpart + (long long)blockIdx.x * BQ * WQ;
    #pragma unroll
    for (int mt = 0; mt < 2; mt++) {
        int b = mB2 + mt * 16 + (lane >> 2);
        #pragma unroll
        for (int nt = 0; nt < 8; nt++) {
            int col = nB2 + nt * 8 + (lane & 3) * 2;
            *(float2*)&dst[b * WQ + col] = make_float2(racc[mt][nt][0], racc[mt][nt][1]);
            *(float2*)&dst[(b + 8) * WQ + col] = make_float2(racc[mt][nt][2], racc[mt][nt][3]);
        }
    }
}

__global__ __launch_bounds__(256) void k_rvreduce() {
    __shared__ float4 red[32][8];
    int tid = threadIdx.x;
    int outIdx = blockIdx.x * 32 + (tid >> 3);
    int sub = tid & 7;
    const float4* p = (const float4*)sc_rvpart;
    float4 s = make_float4(0.f, 0.f, 0.f, 0.f);
    #pragma unroll 4
    for (int i = 0; i < 16; i++) {
        float4 t = p[(long long)(sub + i * 8) * 4096 + outIdx];
        s.x += t.x; s.y += t.y; s.z += t.z; s.w += t.w;
    }
    red[tid >> 3][sub] = s;
    __syncthreads();
    if (sub == 0) {
        float4 a = make_float4(0.f, 0.f, 0.f, 0.f);
        #pragma unroll
        for (int i = 0; i < 8; i++) {
            float4 t = red[tid >> 3][i];
            a.x += t.x; a.y += t.y; a.z += t.z; a.w += t.w;
        }
        int b = outIdx >> 5;
        int c0 = (outIdx & 31) * 4;
        __nv_bfloat16 h0, l0, h1, l1, h2, l2, h3, l3;
        bsplit(a.x, &h0, &l0);
        bsplit(a.y, &h1, &l1);
        bsplit(a.z, &h2, &l2);
        bsplit(a.w, &h3, &l3);
        int o = b * KR + c0;
        st_bf2(&sc_AH[o], h0, h1);
        st_bf2(&sc_AH[o + 2], h2, h3);
        st_bf2(&sc_AL[o], l0, l1);
        st_bf2(&sc_AL[o + 2], l2, l3);
    }
}

// ---------------- host launcher ----------------
extern "C" void kernel_launch(void* const* d_in, const int* in_sizes, int n_in,
                              void* d_out, int out_size) {
    const float* x = (const float*)d_in[0];
    const float* memory = (const float*)d_in[1];
    const float* Wih = (const float*)d_in[2];
    const float* Whh = (const float*)d_in[3];
    const float* bih = (const float*)d_in[4];
    const float* bhh = (const float*)d_in[5];
    const float* Wout = (const float*)d_in[6];
    const float* bout = (const float*)d_in[7];
    const float* rkW = (const float*)d_in[8];
    const float* rkb = (const float*)d_in[9];
    const float* rbW = (const float*)d_in[10];
    const float* rbb = (const float*)d_in[11];
    const float* rgW = (const float*)d_in[12];
    const float* rgb = (const float*)d_in[13];
    const float* wkW = (const float*)d_in[14];
    const float* wkb = (const float*)d_in[15];
    const float* wbW = (const float*)d_in[16];
    const float* wbb = (const float*)d_in[17];
    const float* wgW = (const float*)d_in[18];
    const float* wgb = (const float*)d_in[19];
    const float* erW = (const float*)d_in[20];
    const float* erb = (const float*)d_in[21];
    const float* adW = (const float*)d_in[22];
    const float* adb = (const float*)d_in[23];
    const float* pW = (const float*)d_in[24];
    const float* pb = (const float*)d_in[25];
    float* out = (float*)d_out;

    cudaFuncSetAttribute(k_lstm_mma, cudaFuncAttributeMaxDynamicSharedMemorySize, 2 * L_BUFB);
    cudaFuncSetAttribute(k_ho_mma, cudaFuncAttributeMaxDynamicSharedMemorySize, 2 * L_BUFB);
    cudaFuncSetAttribute(k_sim_mma, cudaFuncAttributeMaxDynamicSharedMemorySize, SIM_TOT);
    cudaFuncSetAttribute(k_memupd_rv, cudaFuncAttributeMaxDynamicSharedMemorySize, MU_TOTAL);

    long long setup_total = (long long)G4 * K1 + G4 + (long long)CP * HQ + (long long)HRP * CP;
    k_setup_w<<<(int)((setup_total + 255) / 256), 256>>>(Wih, Whh, bih, bhh, Wout,
                                                         rkW, rbW, rgW, wkW, wbW, wgW, erW, adW);
    long long sx_total = (long long)SQ * BQ * INQ + 2LL * (HOWP - HOW) * HQ;
    k_setup_x<<<(int)((sx_total + 255) / 256), 256>>>(x);
    k_initmem<<<2048 + 17984, 256>>>(memory);
    k_biases<<<HOW, 128>>>(bout, pW, pb, rkW, rbW, rgW, wkW, wbW, wgW, erW, adW,
                           rkb, rbb, rgb, wkb, wbb, wgb, erb, adb);
    k_fold<<<dim3(HQ / 32, 34), 256>>>(pW, Wout);

    for (int s = 0; s < SQ; s++) {
        k_lstm_mma<<<dim3(G4 / 128, 1, NZ), 256, 2 * L_BUFB>>>(s);
        k_gates<<<(BQ * HQ + 255) / 256, 256>>>();
        k_ho_mma<<<dim3(HOWP / 128, 1, 8), 256, 2 * L_BUFB>>>();
        k_hored<<<BQ, 128>>>(out, s);
        k_sim_mma<<<dim3(64, 2), 256, SIM_TOT>>>();
        k_softmax512<<<2 * BQ, 512>>>();
        k_memupd_rv<<<NQ / 128, 256, MU_TOTAL>>>();
        k_rvreduce<<<128, 256>>>();
    }
}